// round 2
// baseline (speedup 1.0000x reference)
#include <cuda_runtime.h>
#include <math.h>

#define E    1024
#define Dh   64
#define H    16
#define Ff   4096
#define Bb   2
#define Ss   2048
#define NT   (Bb*Ss)     // 4096 tokens
#define EPS  1e-5f

// ---------------- scratch (static device memory; no allocation) ----------------
__device__ float g_h   [NT * E];        // LN1 output
__device__ float g_qkv [NT * 3 * E];    // fused q|k|v, row stride 3072
__device__ float g_Wqkv[E * 3 * E];     // packed [E, 3072]
__device__ float g_bqkv[3 * E];
__device__ float g_o   [NT * E];        // attention out (heads concat)
__device__ float g_x1  [NT * E];        // after first residual
__device__ float g_h2  [NT * E];        // LN2 output
__device__ float g_m1  [NT * Ff];       // relu(h2 @ W1 + b1)

// ---------------- weight packing: Wq/Wk/Wv [H,E,D] -> [E, 3*H*D] ----------------
__global__ void pack_w_kernel(const float* __restrict__ Wq, const float* __restrict__ Wk,
                              const float* __restrict__ Wv, const float* __restrict__ bq,
                              const float* __restrict__ bk, const float* __restrict__ bv) {
    int i = blockIdx.x * blockDim.x + threadIdx.x;
    if (i < E * 3 * E) {
        int e  = i / (3 * E);
        int c  = i % (3 * E);
        int wh = c / E;          // 0=q 1=k 2=v
        int hd = c % E;
        int h  = hd >> 6, d = hd & 63;
        const float* W = (wh == 0) ? Wq : (wh == 1) ? Wk : Wv;
        g_Wqkv[i] = W[(h * E + e) * Dh + d];
    }
    if (i < 3 * E) {
        const float* bs = (i < E) ? bq : (i < 2 * E) ? bk : bv;
        g_bqkv[i] = bs[i % E];
    }
}

// ---------------- layernorm: one block per row of 1024 ----------------
__global__ void ln_kernel(const float* __restrict__ x, const float* __restrict__ g,
                          const float* __restrict__ b, float* __restrict__ out) {
    int row = blockIdx.x;
    int tid = threadIdx.x;                      // 256 threads, 4 floats each
    const float4 v = ((const float4*)(x + (size_t)row * E))[tid];
    float s  = v.x + v.y + v.z + v.w;
    float ss = v.x * v.x + v.y * v.y + v.z * v.z + v.w * v.w;
    #pragma unroll
    for (int o = 16; o; o >>= 1) {
        s  += __shfl_xor_sync(0xffffffffu, s,  o);
        ss += __shfl_xor_sync(0xffffffffu, ss, o);
    }
    __shared__ float sm[8], sm2[8];
    if ((tid & 31) == 0) { sm[tid >> 5] = s; sm2[tid >> 5] = ss; }
    __syncthreads();
    float tot = 0.f, tot2 = 0.f;
    #pragma unroll
    for (int i = 0; i < 8; i++) { tot += sm[i]; tot2 += sm2[i]; }
    float mean = tot * (1.0f / E);
    float var  = tot2 * (1.0f / E) - mean * mean;
    float inv  = rsqrtf(var + EPS);
    const float4 gg = ((const float4*)g)[tid];
    const float4 bb = ((const float4*)b)[tid];
    float4 o;
    o.x = (v.x - mean) * inv * gg.x + bb.x;
    o.y = (v.y - mean) * inv * gg.y + bb.y;
    o.z = (v.z - mean) * inv * gg.z + bb.z;
    o.w = (v.w - mean) * inv * gg.w + bb.w;
    ((float4*)(out + (size_t)row * E))[tid] = o;
}

// ---------------- generic tiled SGEMM: C = A[M,K] @ B[K,N] (+bias)(+relu)(+res) --
template<bool RELU>
__global__ __launch_bounds__(256)
void gemm_kernel(const float* __restrict__ A, const float* __restrict__ Bm,
                 const float* __restrict__ bias, const float* __restrict__ res,
                 float* __restrict__ C, int M, int N, int K) {
    __shared__ float As[16][64];   // [k][m]
    __shared__ float Bs[16][64];   // [k][n]
    int tid = threadIdx.x;
    int tx = tid & 15, ty = tid >> 4;
    int n0 = blockIdx.x * 64, m0 = blockIdx.y * 64;

    int ar = tid >> 2, ac4 = tid & 3;   // A loads: 64 rows x 4 float4
    int br = tid >> 4, bc4 = tid & 15;  // B loads: 16 rows x 16 float4

    float acc[4][4] = {};

    for (int k0 = 0; k0 < K; k0 += 16) {
        float4 a4 = *(const float4*)&A[(size_t)(m0 + ar) * K + k0 + ac4 * 4];
        As[ac4 * 4 + 0][ar] = a4.x;
        As[ac4 * 4 + 1][ar] = a4.y;
        As[ac4 * 4 + 2][ar] = a4.z;
        As[ac4 * 4 + 3][ar] = a4.w;
        *(float4*)&Bs[br][bc4 * 4] = *(const float4*)&Bm[(size_t)(k0 + br) * N + n0 + bc4 * 4];
        __syncthreads();
        #pragma unroll
        for (int k = 0; k < 16; k++) {
            float4 a = *(float4*)&As[k][ty * 4];
            float4 b = *(float4*)&Bs[k][tx * 4];
            acc[0][0] += a.x * b.x; acc[0][1] += a.x * b.y; acc[0][2] += a.x * b.z; acc[0][3] += a.x * b.w;
            acc[1][0] += a.y * b.x; acc[1][1] += a.y * b.y; acc[1][2] += a.y * b.z; acc[1][3] += a.y * b.w;
            acc[2][0] += a.z * b.x; acc[2][1] += a.z * b.y; acc[2][2] += a.z * b.z; acc[2][3] += a.z * b.w;
            acc[3][0] += a.w * b.x; acc[3][1] += a.w * b.y; acc[3][2] += a.w * b.z; acc[3][3] += a.w * b.w;
        }
        __syncthreads();
    }

    const float4 bv4 = *(const float4*)&bias[n0 + tx * 4];
    #pragma unroll
    for (int i = 0; i < 4; i++) {
        int row = m0 + ty * 4 + i;
        float4 v;
        v.x = acc[i][0] + bv4.x;
        v.y = acc[i][1] + bv4.y;
        v.z = acc[i][2] + bv4.z;
        v.w = acc[i][3] + bv4.w;
        if (RELU) {
            v.x = fmaxf(v.x, 0.f); v.y = fmaxf(v.y, 0.f);
            v.z = fmaxf(v.z, 0.f); v.w = fmaxf(v.w, 0.f);
        }
        if (res) {
            float4 rr = *(const float4*)&res[(size_t)row * N + n0 + tx * 4];
            v.x += rr.x; v.y += rr.y; v.z += rr.z; v.w += rr.w;
        }
        *(float4*)&C[(size_t)row * N + n0 + tx * 4] = v;
    }
}

// ---------------- flash-style attention (roles: rows = keys, softmax over queries)
// scores[s,t] = <K[s], Q[t]>, softmax over t, O[s] = sum_t P[s,t] V[t]
__global__ __launch_bounds__(128, 2)
void attn_kernel(const float* __restrict__ qkv, float* __restrict__ o_out) {
    int hb = blockIdx.y;
    int hh = hb >> 1, b = hb & 1;
    int s0 = blockIdx.x * 64;
    int tid  = threadIdx.x;
    int r    = tid >> 1;      // row within 64-row key tile
    int half = tid & 1;       // which 32-col half of scores / output dims

    __shared__ float QP[64][68];   // Q tile, later reused for P tile
    __shared__ float Vt[64][68];

    int nrow = b * Ss + s0 + r;
    const float* Krow = qkv + (size_t)nrow * 3072 + 1024 + hh * 64;
    float4 kreg[16];
    #pragma unroll
    for (int i = 0; i < 16; i++) kreg[i] = *(const float4*)(Krow + i * 4);

    float m = -1e30f, l = 0.f;
    float o[32];
    #pragma unroll
    for (int i = 0; i < 32; i++) o[i] = 0.f;

    const float* Qbase = qkv + (size_t)(b * Ss) * 3072 + hh * 64;
    const float* Vbase = qkv + (size_t)(b * Ss) * 3072 + 2048 + hh * 64;

    for (int t0 = 0; t0 < Ss; t0 += 64) {
        __syncthreads();   // prior AV done before overwriting tiles
        #pragma unroll
        for (int i = 0; i < 8; i++) {
            int idx  = i * 128 + tid;          // 0..1023 float4 slots
            int trow = idx >> 4;
            int c4   = idx & 15;
            *(float4*)&QP[trow][c4 * 4] = *(const float4*)(Qbase + (size_t)(t0 + trow) * 3072 + c4 * 4);
            *(float4*)&Vt[trow][c4 * 4] = *(const float4*)(Vbase + (size_t)(t0 + trow) * 3072 + c4 * 4);
        }
        __syncthreads();

        float s[32];
        float mloc = -1e30f;
        #pragma unroll
        for (int tt = 0; tt < 32; tt++) {
            int t = half * 32 + tt;
            float acc = 0.f;
            #pragma unroll
            for (int i = 0; i < 16; i++) {
                float4 q = *(float4*)&QP[t][i * 4];
                acc += kreg[i].x * q.x + kreg[i].y * q.y + kreg[i].z * q.z + kreg[i].w * q.w;
            }
            s[tt] = acc;
            mloc = fmaxf(mloc, acc);
        }
        __syncthreads();   // all score reads of QP done -> safe to overlay P

        mloc = fmaxf(mloc, __shfl_xor_sync(0xffffffffu, mloc, 1));
        float mnew  = fmaxf(m, mloc);
        float alpha = __expf(m - mnew);
        l *= alpha;
        #pragma unroll
        for (int i = 0; i < 32; i++) o[i] *= alpha;

        float psum = 0.f;
        #pragma unroll
        for (int tt = 0; tt < 32; tt++) {
            float p = __expf(s[tt] - mnew);
            QP[r][half * 32 + tt] = p;        // P overlaid on Q tile
            psum += p;
        }
        psum += __shfl_xor_sync(0xffffffffu, psum, 1);
        l += psum;
        m = mnew;
        __syncwarp();      // partner's P half visible

        #pragma unroll
        for (int tt = 0; tt < 64; tt++) {
            float p = QP[r][tt];
            #pragma unroll
            for (int d4 = 0; d4 < 8; d4++) {
                float4 v = *(float4*)&Vt[tt][half * 32 + d4 * 4];
                o[d4 * 4 + 0] += p * v.x;
                o[d4 * 4 + 1] += p * v.y;
                o[d4 * 4 + 2] += p * v.z;
                o[d4 * 4 + 3] += p * v.w;
            }
        }
    }

    float inv = 1.f / l;
    float* od = o_out + (size_t)nrow * E + hh * 64 + half * 32;
    #pragma unroll
    for (int d4 = 0; d4 < 8; d4++) {
        float4 v;
        v.x = o[d4 * 4 + 0] * inv;
        v.y = o[d4 * 4 + 1] * inv;
        v.z = o[d4 * 4 + 2] * inv;
        v.w = o[d4 * 4 + 3] * inv;
        *(float4*)(od + d4 * 4) = v;
    }
}

// ---------------- host launch ----------------
extern "C" void kernel_launch(void* const* d_in, const int* in_sizes, int n_in,
                              void* d_out, int out_size) {
    const float* x     = (const float*)d_in[0];
    const float* Wq    = (const float*)d_in[1];
    const float* bq    = (const float*)d_in[2];
    const float* Wk    = (const float*)d_in[3];
    const float* bk    = (const float*)d_in[4];
    const float* Wv    = (const float*)d_in[5];
    const float* bv    = (const float*)d_in[6];
    const float* Wo    = (const float*)d_in[7];
    const float* bo    = (const float*)d_in[8];
    const float* ln1_g = (const float*)d_in[9];
    const float* ln1_b = (const float*)d_in[10];
    const float* ln2_g = (const float*)d_in[11];
    const float* ln2_b = (const float*)d_in[12];
    const float* W1    = (const float*)d_in[13];
    const float* b1    = (const float*)d_in[14];
    const float* W2    = (const float*)d_in[15];
    const float* b2    = (const float*)d_in[16];
    float* out = (float*)d_out;

    float *p_h, *p_qkv, *p_Wqkv, *p_bqkv, *p_o, *p_x1, *p_h2, *p_m1;
    cudaGetSymbolAddress((void**)&p_h,    g_h);
    cudaGetSymbolAddress((void**)&p_qkv,  g_qkv);
    cudaGetSymbolAddress((void**)&p_Wqkv, g_Wqkv);
    cudaGetSymbolAddress((void**)&p_bqkv, g_bqkv);
    cudaGetSymbolAddress((void**)&p_o,    g_o);
    cudaGetSymbolAddress((void**)&p_x1,   g_x1);
    cudaGetSymbolAddress((void**)&p_h2,   g_h2);
    cudaGetSymbolAddress((void**)&p_m1,   g_m1);

    // 1. pack fused QKV weight + bias
    pack_w_kernel<<<(E * 3 * E + 255) / 256, 256>>>(Wq, Wk, Wv, bq, bk, bv);

    // 2. LN1
    ln_kernel<<<NT, 256>>>(x, ln1_g, ln1_b, p_h);

    // 3. fused QKV projection: [4096,1024] @ [1024,3072]
    gemm_kernel<false><<<dim3(3 * E / 64, NT / 64), 256>>>(p_h, p_Wqkv, p_bqkv, nullptr, p_qkv, NT, 3 * E, E);

    // 4. attention
    attn_kernel<<<dim3(Ss / 64, H * Bb), 128>>>(p_qkv, p_o);

    // 5. output projection + residual
    gemm_kernel<false><<<dim3(E / 64, NT / 64), 256>>>(p_o, Wo, bo, x, p_x1, NT, E, E);

    // 6. LN2
    ln_kernel<<<NT, 256>>>(p_x1, ln2_g, ln2_b, p_h2);

    // 7. MLP up + ReLU
    gemm_kernel<true><<<dim3(Ff / 64, NT / 64), 256>>>(p_h2, W1, b1, nullptr, p_m1, NT, Ff, E);

    // 8. MLP down + residual -> output
    gemm_kernel<false><<<dim3(E / 64, NT / 64), 256>>>(p_m1, W2, b2, p_x1, out, NT, E, Ff);
}

// round 5
// speedup vs baseline: 1.7860x; 1.7860x over previous
#include <cuda_runtime.h>
#include <cstdint>
#include <math.h>

#define E    1024
#define Dh   64
#define H    16
#define Ff   4096
#define Bb   2
#define Ss   2048
#define NT   (Bb*Ss)     // 4096 tokens
#define EPS  1e-5f

// ---------------- scratch (static device memory; no allocation) ----------------
__device__ float g_h   [NT * E];        // LN1 output (tf32-rounded)
__device__ float g_qkv [NT * 3 * E];    // fused q|k|v, row stride 3072
__device__ float g_Wqkv[3 * E * E];     // packed W_qkv^T : [3072, 1024] (N,K) tf32
__device__ float g_bqkv[3 * E];
__device__ float g_WoT [E * E];         // Wo^T  [1024,1024] tf32
__device__ float g_W1T [Ff * E];        // W1^T  [4096,1024] tf32
__device__ float g_W2T [E * Ff];        // W2^T  [1024,4096] tf32
__device__ float g_o   [NT * E];        // attention out (tf32-rounded)
__device__ float g_x1  [NT * E];        // after first residual (fp32)
__device__ float g_h2  [NT * E];        // LN2 output (tf32-rounded)
__device__ float g_m1  [NT * Ff];       // relu(h2 @ W1 + b1) (tf32-rounded)

// ======================= helpers =======================
__device__ __forceinline__ uint32_t smem_u32(const void* p) {
    uint32_t a;
    asm("{ .reg .u64 t; cvta.to.shared.u64 t, %1; cvt.u32.u64 %0, t; }" : "=r"(a) : "l"(p));
    return a;
}
__device__ __forceinline__ float rtf32(float x) {
    uint32_t u;
    asm("cvt.rna.tf32.f32 %0, %1;" : "=r"(u) : "f"(x));
    return __uint_as_float(u);
}
#define CP_ASYNC16(dst, src) \
    asm volatile("cp.async.cg.shared.global [%0], [%1], 16;" :: "r"((uint32_t)(dst)), "l"(src))
#define CP_COMMIT() asm volatile("cp.async.commit_group;" ::: "memory")
#define CP_WAIT0()  asm volatile("cp.async.wait_group 0;" ::: "memory")

// m16n8k8 tf32 mma: D(f32) += A(tf32) * B(tf32)
__device__ __forceinline__ void mma_tf32(float* c, const uint32_t* a, uint32_t b0, uint32_t b1) {
    asm volatile(
        "mma.sync.aligned.m16n8k8.row.col.f32.tf32.tf32.f32 "
        "{%0,%1,%2,%3}, {%4,%5,%6,%7}, {%8,%9}, {%0,%1,%2,%3};"
        : "+f"(c[0]), "+f"(c[1]), "+f"(c[2]), "+f"(c[3])
        : "r"(a[0]), "r"(a[1]), "r"(a[2]), "r"(a[3]), "r"(b0), "r"(b1));
}

// ---------------- weight packing (tf32-rounded) ----------------
__global__ void pack_qkv_kernel(const float* __restrict__ Wq, const float* __restrict__ Wk,
                                const float* __restrict__ Wv, const float* __restrict__ bq,
                                const float* __restrict__ bk, const float* __restrict__ bv) {
    int i = blockIdx.x * blockDim.x + threadIdx.x;
    if (i < 3 * E * E) {
        int n = i >> 10;            // 0..3071
        int e = i & 1023;
        int wh = n >> 10;           // 0=q 1=k 2=v
        int hd = n & 1023;
        int h = hd >> 6, d = hd & 63;
        const float* W = (wh == 0) ? Wq : (wh == 1) ? Wk : Wv;
        g_Wqkv[i] = rtf32(W[(h * E + e) * Dh + d]);
    }
    if (i < 3 * E) {
        const float* bs = (i < E) ? bq : (i < 2 * E) ? bk : bv;
        g_bqkv[i] = bs[i % E];
    }
}

// out[n*K + k] = tf32(in[k*N + n])
__global__ void transpose_kernel(const float* __restrict__ in, float* __restrict__ out,
                                 int K, int N) {
    __shared__ float t[32][33];
    int k0 = blockIdx.x * 32, n0 = blockIdx.y * 32;
    int x = threadIdx.x, y = threadIdx.y;     // 32 x 8
    #pragma unroll
    for (int i = 0; i < 32; i += 8)
        t[y + i][x] = in[(size_t)(k0 + y + i) * N + n0 + x];
    __syncthreads();
    #pragma unroll
    for (int i = 0; i < 32; i += 8)
        out[(size_t)(n0 + y + i) * K + k0 + x] = rtf32(t[x][y + i]);
}

// ---------------- layernorm (tf32-rounded output) ----------------
__global__ void ln_kernel(const float* __restrict__ x, const float* __restrict__ g,
                          const float* __restrict__ b, float* __restrict__ out) {
    int row = blockIdx.x;
    int tid = threadIdx.x;
    const float4 v = ((const float4*)(x + (size_t)row * E))[tid];
    float s  = v.x + v.y + v.z + v.w;
    float ss = v.x * v.x + v.y * v.y + v.z * v.z + v.w * v.w;
    #pragma unroll
    for (int o = 16; o; o >>= 1) {
        s  += __shfl_xor_sync(0xffffffffu, s,  o);
        ss += __shfl_xor_sync(0xffffffffu, ss, o);
    }
    __shared__ float sm[8], sm2[8];
    if ((tid & 31) == 0) { sm[tid >> 5] = s; sm2[tid >> 5] = ss; }
    __syncthreads();
    float tot = 0.f, tot2 = 0.f;
    #pragma unroll
    for (int i = 0; i < 8; i++) { tot += sm[i]; tot2 += sm2[i]; }
    float mean = tot * (1.0f / E);
    float var  = tot2 * (1.0f / E) - mean * mean;
    float inv  = rsqrtf(var + EPS);
    const float4 gg = ((const float4*)g)[tid];
    const float4 bb = ((const float4*)b)[tid];
    float4 o;
    o.x = rtf32((v.x - mean) * inv * gg.x + bb.x);
    o.y = rtf32((v.y - mean) * inv * gg.y + bb.y);
    o.z = rtf32((v.z - mean) * inv * gg.z + bb.z);
    o.w = rtf32((v.w - mean) * inv * gg.w + bb.w);
    ((float4*)(out + (size_t)row * E))[tid] = o;
}

// ---------------- tf32 warp-MMA GEMM: C = A[M,K] @ Bt[N,K]^T (+bias)(+relu)(+res)
// CTA tile 128x128, 8 warps (32x64 each), K-chunk 32, cp.async double buffer.
// smem row stride 36 floats (144B): conflict-free STS.128 and fragment LDS.
#define LDA 36
#define TILE_BYTES (128 * LDA * 4)      // 18432 per tile
#define BUF_BYTES  (2 * TILE_BYTES)     // A+B per buffer

template<bool RELU, bool ROUND>
__global__ __launch_bounds__(256)
void gemm_tc(const float* __restrict__ A, const float* __restrict__ Bt,
             const float* __restrict__ bias, const float* __restrict__ res,
             float* __restrict__ C, int M, int N, int K) {
    extern __shared__ char smem[];
    uint32_t sb = smem_u32(smem);
    int tid = threadIdx.x;
    int lane = tid & 31, wid = tid >> 5;
    int warp_m = wid & 3, warp_n = wid >> 2;        // 4 x 2 warp grid
    int n0 = blockIdx.x * 128, m0 = blockIdx.y * 128;

    // gmem row pointers for this thread's cp.async slice
    // idx = tid + i*256 (i<4): row = idx>>3, k4 = idx&7
    const float* Abase = A  + (size_t)m0 * K;
    const float* Bbase = Bt + (size_t)n0 * K;

    int NC = K >> 5;

    // prologue: chunk 0 -> buffer 0
    #pragma unroll
    for (int i = 0; i < 4; i++) {
        int idx = tid + i * 256;
        int row = idx >> 3, k4 = idx & 7;
        uint32_t doff = row * (LDA * 4) + k4 * 16;
        CP_ASYNC16(sb + doff,              Abase + (size_t)row * K + k4 * 4);
        CP_ASYNC16(sb + TILE_BYTES + doff, Bbase + (size_t)row * K + k4 * 4);
    }
    CP_COMMIT(); CP_WAIT0();
    __syncthreads();

    float acc[2][8][4] = {};

    for (int c = 0; c < NC; c++) {
        if (c + 1 < NC) {
            uint32_t bufo = ((c + 1) & 1) * BUF_BYTES;
            const float* as = Abase + (c + 1) * 32;
            const float* bs = Bbase + (c + 1) * 32;
            #pragma unroll
            for (int i = 0; i < 4; i++) {
                int idx = tid + i * 256;
                int row = idx >> 3, k4 = idx & 7;
                uint32_t doff = bufo + row * (LDA * 4) + k4 * 16;
                CP_ASYNC16(sb + doff,              as + (size_t)row * K + k4 * 4);
                CP_ASYNC16(sb + TILE_BYTES + doff, bs + (size_t)row * K + k4 * 4);
            }
        }
        CP_COMMIT();

        const float* As = (const float*)(smem + (c & 1) * BUF_BYTES);
        const float* Bs = As + 128 * LDA;

        int r = lane >> 2, cc = lane & 3;
        #pragma unroll
        for (int kk = 0; kk < 4; kk++) {
            int k0 = kk * 8;
            uint32_t afr[2][4];
            #pragma unroll
            for (int mt = 0; mt < 2; mt++) {
                int rb = warp_m * 32 + mt * 16 + r;
                afr[mt][0] = *(const uint32_t*)&As[(rb    ) * LDA + k0 + cc];
                afr[mt][1] = *(const uint32_t*)&As[(rb + 8) * LDA + k0 + cc];
                afr[mt][2] = *(const uint32_t*)&As[(rb    ) * LDA + k0 + cc + 4];
                afr[mt][3] = *(const uint32_t*)&As[(rb + 8) * LDA + k0 + cc + 4];
            }
            #pragma unroll
            for (int nt = 0; nt < 8; nt++) {
                int nb = warp_n * 64 + nt * 8 + r;        // n index held by this lane
                uint32_t b0 = *(const uint32_t*)&Bs[nb * LDA + k0 + cc];
                uint32_t b1 = *(const uint32_t*)&Bs[nb * LDA + k0 + cc + 4];
                mma_tf32(acc[0][nt], afr[0], b0, b1);
                mma_tf32(acc[1][nt], afr[1], b0, b1);
            }
        }
        CP_WAIT0();
        __syncthreads();
    }

    // epilogue
    int r = lane >> 2, cc = lane & 3;
    #pragma unroll
    for (int mt = 0; mt < 2; mt++) {
        #pragma unroll
        for (int nt = 0; nt < 8; nt++) {
            int col = n0 + warp_n * 64 + nt * 8 + cc * 2;
            float2 bv = *(const float2*)&bias[col];
            #pragma unroll
            for (int rr = 0; rr < 2; rr++) {
                int row = m0 + warp_m * 32 + mt * 16 + r + rr * 8;
                float2 v;
                v.x = acc[mt][nt][rr * 2 + 0] + bv.x;
                v.y = acc[mt][nt][rr * 2 + 1] + bv.y;
                if (RELU) { v.x = fmaxf(v.x, 0.f); v.y = fmaxf(v.y, 0.f); }
                if (res) {
                    float2 rv = *(const float2*)&res[(size_t)row * N + col];
                    v.x += rv.x; v.y += rv.y;
                }
                if (ROUND) { v.x = rtf32(v.x); v.y = rtf32(v.y); }
                *(float2*)&C[(size_t)row * N + col] = v;
            }
        }
    }
}

// ---------------- flash-style attention (rows = keys, softmax over queries) -----
__global__ __launch_bounds__(128, 2)
void attn_kernel(const float* __restrict__ qkv, float* __restrict__ o_out) {
    int hb = blockIdx.y;
    int hh = hb >> 1, b = hb & 1;
    int s0 = blockIdx.x * 64;
    int tid  = threadIdx.x;
    int r    = tid >> 1;
    int half = tid & 1;

    __shared__ float QP[64][68];
    __shared__ float Vt[64][68];

    int nrow = b * Ss + s0 + r;
    const float* Krow = qkv + (size_t)nrow * 3072 + 1024 + hh * 64;
    float4 kreg[16];
    #pragma unroll
    for (int i = 0; i < 16; i++) kreg[i] = *(const float4*)(Krow + i * 4);

    float m = -1e30f, l = 0.f;
    float o[32];
    #pragma unroll
    for (int i = 0; i < 32; i++) o[i] = 0.f;

    const float* Qbase = qkv + (size_t)(b * Ss) * 3072 + hh * 64;
    const float* Vbase = qkv + (size_t)(b * Ss) * 3072 + 2048 + hh * 64;

    for (int t0 = 0; t0 < Ss; t0 += 64) {
        __syncthreads();
        #pragma unroll
        for (int i = 0; i < 8; i++) {
            int idx  = i * 128 + tid;
            int trow = idx >> 4;
            int c4   = idx & 15;
            *(float4*)&QP[trow][c4 * 4] = *(const float4*)(Qbase + (size_t)(t0 + trow) * 3072 + c4 * 4);
            *(float4*)&Vt[trow][c4 * 4] = *(const float4*)(Vbase + (size_t)(t0 + trow) * 3072 + c4 * 4);
        }
        __syncthreads();

        float s[32];
        float mloc = -1e30f;
        #pragma unroll
        for (int tt = 0; tt < 32; tt++) {
            int t = half * 32 + tt;
            float acc = 0.f;
            #pragma unroll
            for (int i = 0; i < 16; i++) {
                float4 q = *(float4*)&QP[t][i * 4];
                acc += kreg[i].x * q.x + kreg[i].y * q.y + kreg[i].z * q.z + kreg[i].w * q.w;
            }
            s[tt] = acc;
            mloc = fmaxf(mloc, acc);
        }
        __syncthreads();

        mloc = fmaxf(mloc, __shfl_xor_sync(0xffffffffu, mloc, 1));
        float mnew  = fmaxf(m, mloc);
        float alpha = __expf(m - mnew);
        l *= alpha;
        #pragma unroll
        for (int i = 0; i < 32; i++) o[i] *= alpha;

        float psum = 0.f;
        #pragma unroll
        for (int tt = 0; tt < 32; tt++) {
            float p = __expf(s[tt] - mnew);
            QP[r][half * 32 + tt] = p;
            psum += p;
        }
        psum += __shfl_xor_sync(0xffffffffu, psum, 1);
        l += psum;
        m = mnew;
        __syncwarp();

        #pragma unroll
        for (int tt = 0; tt < 64; tt++) {
            float p = QP[r][tt];
            #pragma unroll
            for (int d4 = 0; d4 < 8; d4++) {
                float4 v = *(float4*)&Vt[tt][half * 32 + d4 * 4];
                o[d4 * 4 + 0] += p * v.x;
                o[d4 * 4 + 1] += p * v.y;
                o[d4 * 4 + 2] += p * v.z;
                o[d4 * 4 + 3] += p * v.w;
            }
        }
    }

    float inv = 1.f / l;
    float* od = o_out + (size_t)nrow * E + hh * 64 + half * 32;
    #pragma unroll
    for (int d4 = 0; d4 < 8; d4++) {
        float4 v;
        v.x = rtf32(o[d4 * 4 + 0] * inv);
        v.y = rtf32(o[d4 * 4 + 1] * inv);
        v.z = rtf32(o[d4 * 4 + 2] * inv);
        v.w = rtf32(o[d4 * 4 + 3] * inv);
        *(float4*)(od + d4 * 4) = v;
    }
}

// ---------------- host launch ----------------
extern "C" void kernel_launch(void* const* d_in, const int* in_sizes, int n_in,
                              void* d_out, int out_size) {
    const float* x     = (const float*)d_in[0];
    const float* Wq    = (const float*)d_in[1];
    const float* bq    = (const float*)d_in[2];
    const float* Wk    = (const float*)d_in[3];
    const float* bk    = (const float*)d_in[4];
    const float* Wv    = (const float*)d_in[5];
    const float* bv    = (const float*)d_in[6];
    const float* Wo    = (const float*)d_in[7];
    const float* bo    = (const float*)d_in[8];
    const float* ln1_g = (const float*)d_in[9];
    const float* ln1_b = (const float*)d_in[10];
    const float* ln2_g = (const float*)d_in[11];
    const float* ln2_b = (const float*)d_in[12];
    const float* W1    = (const float*)d_in[13];
    const float* b1    = (const float*)d_in[14];
    const float* W2    = (const float*)d_in[15];
    const float* b2    = (const float*)d_in[16];
    float* out = (float*)d_out;

    float *p_h, *p_qkv, *p_Wqkv, *p_bqkv, *p_WoT, *p_W1T, *p_W2T, *p_o, *p_x1, *p_h2, *p_m1;
    cudaGetSymbolAddress((void**)&p_h,    g_h);
    cudaGetSymbolAddress((void**)&p_qkv,  g_qkv);
    cudaGetSymbolAddress((void**)&p_Wqkv, g_Wqkv);
    cudaGetSymbolAddress((void**)&p_bqkv, g_bqkv);
    cudaGetSymbolAddress((void**)&p_WoT,  g_WoT);
    cudaGetSymbolAddress((void**)&p_W1T,  g_W1T);
    cudaGetSymbolAddress((void**)&p_W2T,  g_W2T);
    cudaGetSymbolAddress((void**)&p_o,    g_o);
    cudaGetSymbolAddress((void**)&p_x1,   g_x1);
    cudaGetSymbolAddress((void**)&p_h2,   g_h2);
    cudaGetSymbolAddress((void**)&p_m1,   g_m1);

    const int SMEM_SZ = 2 * BUF_BYTES;  // 73728
    cudaFuncSetAttribute(gemm_tc<false, false>, cudaFuncAttributeMaxDynamicSharedMemorySize, SMEM_SZ);
    cudaFuncSetAttribute(gemm_tc<true,  true>,  cudaFuncAttributeMaxDynamicSharedMemorySize, SMEM_SZ);

    // 1. pack fused QKV weight (transposed, tf32) + bias; transpose Wo, W1, W2 (tf32)
    pack_qkv_kernel<<<(3 * E * E + 255) / 256, 256>>>(Wq, Wk, Wv, bq, bk, bv);
    transpose_kernel<<<dim3(E / 32, E / 32),  dim3(32, 8)>>>(Wo, p_WoT, E, E);
    transpose_kernel<<<dim3(E / 32, Ff / 32), dim3(32, 8)>>>(W1, p_W1T, E, Ff);
    transpose_kernel<<<dim3(Ff / 32, E / 32), dim3(32, 8)>>>(W2, p_W2T, Ff, E);

    // 2. LN1
    ln_kernel<<<NT, 256>>>(x, ln1_g, ln1_b, p_h);

    // 3. fused QKV projection: [4096,1024] @ [1024,3072]
    gemm_tc<false, false><<<dim3(3 * E / 128, NT / 128), 256, SMEM_SZ>>>(p_h, p_Wqkv, p_bqkv, nullptr, p_qkv, NT, 3 * E, E);

    // 4. attention
    attn_kernel<<<dim3(Ss / 64, H * Bb), 128>>>(p_qkv, p_o);

    // 5. output projection + residual
    gemm_tc<false, false><<<dim3(E / 128, NT / 128), 256, SMEM_SZ>>>(p_o, p_WoT, bo, x, p_x1, NT, E, E);

    // 6. LN2
    ln_kernel<<<NT, 256>>>(p_x1, ln2_g, ln2_b, p_h2);

    // 7. MLP up + ReLU (output tf32-rounded: feeds GEMM 8 as A)
    gemm_tc<true, true><<<dim3(Ff / 128, NT / 128), 256, SMEM_SZ>>>(p_h2, p_W1T, b1, nullptr, p_m1, NT, Ff, E);

    // 8. MLP down + residual -> output
    gemm_tc<false, false><<<dim3(E / 128, NT / 128), 256, SMEM_SZ>>>(p_m1, p_W2T, b2, p_x1, out, NT, E, Ff);
}

// round 7
// speedup vs baseline: 3.9119x; 2.1903x over previous
#include <cuda_runtime.h>
#include <cstdint>
#include <math.h>

#define E    1024
#define Dh   64
#define H    16
#define Ff   4096
#define Bb   2
#define Ss   2048
#define NT   (Bb*Ss)     // 4096 tokens
#define EPS  1e-5f

// ---------------- scratch (static device memory; no allocation) ----------------
__device__ float g_h   [NT * E];        // LN1 output (tf32-rounded)
__device__ float g_qkv [NT * 3 * E];    // fused q|k|v, row stride 3072 (fp32)
__device__ float g_Wqkv[3 * E * E];     // packed W_qkv^T : [3072, 1024] (N,K) tf32
__device__ float g_bqkv[3 * E];
__device__ float g_WoT [E * E];         // Wo^T  [1024,1024] tf32
__device__ float g_W1T [Ff * E];        // W1^T  [4096,1024] tf32
__device__ float g_W2T [E * Ff];        // W2^T  [1024,4096] tf32
__device__ float g_o   [NT * E];        // attention out (tf32-rounded)
__device__ float g_x1  [NT * E];        // after first residual (fp32)
__device__ float g_h2  [NT * E];        // LN2 output (tf32-rounded)
__device__ float g_m1  [NT * Ff];       // relu(h2 @ W1 + b1) (tf32-rounded)

// ======================= helpers =======================
__device__ __forceinline__ uint32_t smem_u32(const void* p) {
    uint32_t a;
    asm("{ .reg .u64 t; cvta.to.shared.u64 t, %1; cvt.u32.u64 %0, t; }" : "=r"(a) : "l"(p));
    return a;
}
__device__ __forceinline__ float rtf32(float x) {
    uint32_t u;
    asm("cvt.rna.tf32.f32 %0, %1;" : "=r"(u) : "f"(x));
    return __uint_as_float(u);
}
#define CP_ASYNC16(dst, src) \
    asm volatile("cp.async.cg.shared.global [%0], [%1], 16;" :: "r"((uint32_t)(dst)), "l"(src))
#define CP_COMMIT() asm volatile("cp.async.commit_group;" ::: "memory")
#define CP_WAIT0()  asm volatile("cp.async.wait_group 0;" ::: "memory")
#define CP_WAIT1()  asm volatile("cp.async.wait_group 1;" ::: "memory")

// m16n8k8 tf32 mma: D(f32) += A(tf32) * B(tf32)
__device__ __forceinline__ void mma_tf32(float* c, const uint32_t* a, uint32_t b0, uint32_t b1) {
    asm volatile(
        "mma.sync.aligned.m16n8k8.row.col.f32.tf32.tf32.f32 "
        "{%0,%1,%2,%3}, {%4,%5,%6,%7}, {%8,%9}, {%0,%1,%2,%3};"
        : "+f"(c[0]), "+f"(c[1]), "+f"(c[2]), "+f"(c[3])
        : "r"(a[0]), "r"(a[1]), "r"(a[2]), "r"(a[3]), "r"(b0), "r"(b1));
}

// ---------------- weight packing (tf32-rounded) ----------------
__global__ void pack_qkv_kernel(const float* __restrict__ Wq, const float* __restrict__ Wk,
                                const float* __restrict__ Wv, const float* __restrict__ bq,
                                const float* __restrict__ bk, const float* __restrict__ bv) {
    int i = blockIdx.x * blockDim.x + threadIdx.x;
    if (i < 3 * E * E) {
        int n = i >> 10;            // 0..3071
        int e = i & 1023;
        int wh = n >> 10;           // 0=q 1=k 2=v
        int hd = n & 1023;
        int h = hd >> 6, d = hd & 63;
        const float* W = (wh == 0) ? Wq : (wh == 1) ? Wk : Wv;
        g_Wqkv[i] = rtf32(W[(h * E + e) * Dh + d]);
    }
    if (i < 3 * E) {
        const float* bs = (i < E) ? bq : (i < 2 * E) ? bk : bv;
        g_bqkv[i] = bs[i % E];
    }
}

// out[n*K + k] = tf32(in[k*N + n])
__global__ void transpose_kernel(const float* __restrict__ in, float* __restrict__ out,
                                 int K, int N) {
    __shared__ float t[32][33];
    int k0 = blockIdx.x * 32, n0 = blockIdx.y * 32;
    int x = threadIdx.x, y = threadIdx.y;     // 32 x 8
    #pragma unroll
    for (int i = 0; i < 32; i += 8)
        t[y + i][x] = in[(size_t)(k0 + y + i) * N + n0 + x];
    __syncthreads();
    #pragma unroll
    for (int i = 0; i < 32; i += 8)
        out[(size_t)(n0 + y + i) * K + k0 + x] = rtf32(t[x][y + i]);
}

// ---------------- layernorm (tf32-rounded output) ----------------
__global__ void ln_kernel(const float* __restrict__ x, const float* __restrict__ g,
                          const float* __restrict__ b, float* __restrict__ out) {
    int row = blockIdx.x;
    int tid = threadIdx.x;
    const float4 v = ((const float4*)(x + (size_t)row * E))[tid];
    float s  = v.x + v.y + v.z + v.w;
    float ss = v.x * v.x + v.y * v.y + v.z * v.z + v.w * v.w;
    #pragma unroll
    for (int o = 16; o; o >>= 1) {
        s  += __shfl_xor_sync(0xffffffffu, s,  o);
        ss += __shfl_xor_sync(0xffffffffu, ss, o);
    }
    __shared__ float sm[8], sm2[8];
    if ((tid & 31) == 0) { sm[tid >> 5] = s; sm2[tid >> 5] = ss; }
    __syncthreads();
    float tot = 0.f, tot2 = 0.f;
    #pragma unroll
    for (int i = 0; i < 8; i++) { tot += sm[i]; tot2 += sm2[i]; }
    float mean = tot * (1.0f / E);
    float var  = tot2 * (1.0f / E) - mean * mean;
    float inv  = rsqrtf(var + EPS);
    const float4 gg = ((const float4*)g)[tid];
    const float4 bb = ((const float4*)b)[tid];
    float4 o;
    o.x = rtf32((v.x - mean) * inv * gg.x + bb.x);
    o.y = rtf32((v.y - mean) * inv * gg.y + bb.y);
    o.z = rtf32((v.z - mean) * inv * gg.z + bb.z);
    o.w = rtf32((v.w - mean) * inv * gg.w + bb.w);
    ((float4*)(out + (size_t)row * E))[tid] = o;
}

// ---------------- tf32 warp-MMA GEMM: C = A[M,K] @ Bt[N,K]^T (+bias)(+relu)(+res)
// CTA tile 128x128, 8 warps (32x64 each), K-chunk 32, 3-stage cp.async pipeline.
#define LDA 36
#define TILE_BYTES (128 * LDA * 4)      // 18432 per tile
#define BUF_BYTES  (2 * TILE_BYTES)     // A+B per stage
#define GEMM_SMEM  (3 * BUF_BYTES)      // 110592

template<bool RELU, bool ROUND>
__global__ __launch_bounds__(256)
void gemm_tc(const float* __restrict__ A, const float* __restrict__ Bt,
             const float* __restrict__ bias, const float* __restrict__ res,
             float* __restrict__ C, int M, int N, int K) {
    extern __shared__ char smem[];
    uint32_t sb = smem_u32(smem);
    int tid = threadIdx.x;
    int lane = tid & 31, wid = tid >> 5;
    int warp_m = wid & 3, warp_n = wid >> 2;        // 4 x 2 warp grid
    int n0 = blockIdx.x * 128, m0 = blockIdx.y * 128;

    const float* Abase = A  + (size_t)m0 * K;
    const float* Bbase = Bt + (size_t)n0 * K;

    int NC = K >> 5;

    // prologue: chunks 0,1 -> stages 0,1
    #pragma unroll
    for (int i = 0; i < 4; i++) {
        int idx = tid + i * 256;
        int row = idx >> 3, k4 = idx & 7;
        uint32_t doff = row * (LDA * 4) + k4 * 16;
        CP_ASYNC16(sb + doff,              Abase + (size_t)row * K + k4 * 4);
        CP_ASYNC16(sb + TILE_BYTES + doff, Bbase + (size_t)row * K + k4 * 4);
    }
    CP_COMMIT();
    #pragma unroll
    for (int i = 0; i < 4; i++) {
        int idx = tid + i * 256;
        int row = idx >> 3, k4 = idx & 7;
        uint32_t doff = BUF_BYTES + row * (LDA * 4) + k4 * 16;
        CP_ASYNC16(sb + doff,              Abase + (size_t)row * K + 32 + k4 * 4);
        CP_ASYNC16(sb + TILE_BYTES + doff, Bbase + (size_t)row * K + 32 + k4 * 4);
    }
    CP_COMMIT();
    CP_WAIT1();            // stage 0 complete
    __syncthreads();

    float acc[2][8][4] = {};
    int cb = 0, pb = 2;    // compute stage, prefetch stage

    for (int c = 0; c < NC; c++) {
        if (c + 2 < NC) {
            uint32_t bufo = pb * BUF_BYTES;
            const float* as = Abase + (c + 2) * 32;
            const float* bs = Bbase + (c + 2) * 32;
            #pragma unroll
            for (int i = 0; i < 4; i++) {
                int idx = tid + i * 256;
                int row = idx >> 3, k4 = idx & 7;
                uint32_t doff = bufo + row * (LDA * 4) + k4 * 16;
                CP_ASYNC16(sb + doff,              as + (size_t)row * K + k4 * 4);
                CP_ASYNC16(sb + TILE_BYTES + doff, bs + (size_t)row * K + k4 * 4);
            }
        }
        CP_COMMIT();

        const float* As = (const float*)(smem + cb * BUF_BYTES);
        const float* Bs = As + 128 * LDA;

        int r = lane >> 2, cc = lane & 3;
        #pragma unroll
        for (int kk = 0; kk < 4; kk++) {
            int k0 = kk * 8;
            uint32_t afr[2][4];
            #pragma unroll
            for (int mt = 0; mt < 2; mt++) {
                int rb = warp_m * 32 + mt * 16 + r;
                afr[mt][0] = *(const uint32_t*)&As[(rb    ) * LDA + k0 + cc];
                afr[mt][1] = *(const uint32_t*)&As[(rb + 8) * LDA + k0 + cc];
                afr[mt][2] = *(const uint32_t*)&As[(rb    ) * LDA + k0 + cc + 4];
                afr[mt][3] = *(const uint32_t*)&As[(rb + 8) * LDA + k0 + cc + 4];
            }
            #pragma unroll
            for (int nt = 0; nt < 8; nt++) {
                int nb = warp_n * 64 + nt * 8 + r;
                uint32_t b0 = *(const uint32_t*)&Bs[nb * LDA + k0 + cc];
                uint32_t b1 = *(const uint32_t*)&Bs[nb * LDA + k0 + cc + 4];
                mma_tf32(acc[0][nt], afr[0], b0, b1);
                mma_tf32(acc[1][nt], afr[1], b0, b1);
            }
        }
        CP_WAIT1();          // next compute stage resident (one more still in flight)
        __syncthreads();
        cb = (cb + 1 == 3) ? 0 : cb + 1;
        pb = (pb + 1 == 3) ? 0 : pb + 1;
    }

    // epilogue
    int r = lane >> 2, cc = lane & 3;
    #pragma unroll
    for (int mt = 0; mt < 2; mt++) {
        #pragma unroll
        for (int nt = 0; nt < 8; nt++) {
            int col = n0 + warp_n * 64 + nt * 8 + cc * 2;
            float2 bv = *(const float2*)&bias[col];
            #pragma unroll
            for (int rr = 0; rr < 2; rr++) {
                int row = m0 + warp_m * 32 + mt * 16 + r + rr * 8;
                float2 v;
                v.x = acc[mt][nt][rr * 2 + 0] + bv.x;
                v.y = acc[mt][nt][rr * 2 + 1] + bv.y;
                if (RELU) { v.x = fmaxf(v.x, 0.f); v.y = fmaxf(v.y, 0.f); }
                if (res) {
                    float2 rv = *(const float2*)&res[(size_t)row * N + col];
                    v.x += rv.x; v.y += rv.y;
                }
                if (ROUND) { v.x = rtf32(v.x); v.y = rtf32(v.y); }
                *(float2*)&C[(size_t)row * N + col] = v;
            }
        }
    }
}

// ---------------- tf32 MMA flash attention (rows = keys, softmax over queries) --
// CTA: 128 key rows, 8 warps (m16 slab each, K hi/lo frags in regs), t-tiles of 64.
// S computed with 3-term split-tf32 (effectively fp32-accurate scores).
#define LDQ 68
#define LDV 72
#define LDP 68
#define QBUF (64 * LDQ)                  // floats per Q stage
#define VBUF (64 * LDV)
#define ATT_Q_OFF 0
#define ATT_V_OFF (2 * QBUF * 4)
#define ATT_K_OFF ((2 * QBUF + 2 * VBUF) * 4)
#define ATT_SMEM  (ATT_K_OFF + 128 * LDP * 4)   // 106496 bytes

__global__ __launch_bounds__(256)
void attn_mma_kernel(const float* __restrict__ qkv, float* __restrict__ o_out) {
    extern __shared__ float smf[];
    uint32_t sb = smem_u32(smf);
    float* Qs = smf;
    float* Vs = smf + 2 * QBUF;
    float* KP = smf + 2 * QBUF + 2 * VBUF;

    int hb = blockIdx.y;
    int hh = hb >> 1, b = hb & 1;
    int s0 = blockIdx.x * 128;
    int tid = threadIdx.x, lane = tid & 31, wid = tid >> 5;
    int r = lane >> 2, cc = lane & 3;
    int rb = wid * 16 + r;

    const float* base = qkv + (size_t)(b * Ss) * 3072 + hh * 64;

    // stage K tile [128 x 64] (group 0)
    #pragma unroll
    for (int i = 0; i < 8; i++) {
        int idx = tid + i * 256;               // 0..2047
        int row = idx >> 4, c4 = idx & 15;
        CP_ASYNC16(sb + ATT_K_OFF + (row * LDP + c4 * 4) * 4,
                   base + 1024 + (size_t)(s0 + row) * 3072 + c4 * 4);
    }
    CP_COMMIT();
    // prefetch Q/V tile 0 into buffer 0 (group 1)
    #pragma unroll
    for (int i = 0; i < 4; i++) {
        int idx = tid + i * 256;               // 0..1023
        int row = idx >> 4, c4 = idx & 15;
        CP_ASYNC16(sb + ATT_Q_OFF + (row * LDQ + c4 * 4) * 4,
                   base + (size_t)row * 3072 + c4 * 4);
        CP_ASYNC16(sb + ATT_V_OFF + (row * LDV + c4 * 4) * 4,
                   base + 2048 + (size_t)row * 3072 + c4 * 4);
    }
    CP_COMMIT();
    CP_WAIT1();              // K resident
    __syncthreads();

    // K fragments hi/lo in registers: m16 (this warp's rows) x k64
    uint32_t kfh[8][4], kfl[8][4];
    #pragma unroll
    for (int k8 = 0; k8 < 8; k8++) {
        int k0 = k8 * 8;
        float kv[4];
        kv[0] = KP[(rb    ) * LDP + k0 + cc];
        kv[1] = KP[(rb + 8) * LDP + k0 + cc];
        kv[2] = KP[(rb    ) * LDP + k0 + cc + 4];
        kv[3] = KP[(rb + 8) * LDP + k0 + cc + 4];
        #pragma unroll
        for (int j = 0; j < 4; j++) {
            float hi = rtf32(kv[j]);
            kfh[k8][j] = __float_as_uint(hi);
            kfl[k8][j] = __float_as_uint(rtf32(kv[j] - hi));
        }
    }
    __syncthreads();          // KP region now reused as P

    float mrow0 = -1e30f, mrow1 = -1e30f, lrow0 = 0.f, lrow1 = 0.f;
    float o[8][4] = {};

    for (int t0 = 0; t0 < Ss; t0 += 64) {
        int buf = (t0 >> 6) & 1;
        if (t0 + 64 < Ss) {
            int nb = buf ^ 1;
            const float* src = base + (size_t)(t0 + 64) * 3072;
            #pragma unroll
            for (int i = 0; i < 4; i++) {
                int idx = tid + i * 256;
                int row = idx >> 4, c4 = idx & 15;
                CP_ASYNC16(sb + ATT_Q_OFF + nb * QBUF * 4 + (row * LDQ + c4 * 4) * 4,
                           src + (size_t)row * 3072 + c4 * 4);
                CP_ASYNC16(sb + ATT_V_OFF + nb * VBUF * 4 + (row * LDV + c4 * 4) * 4,
                           src + 2048 + (size_t)row * 3072 + c4 * 4);
            }
        }
        CP_COMMIT();

        const float* Qb = Qs + buf * QBUF;
        const float* Vb = Vs + buf * VBUF;

        // S = K x Q^T : [16 rows x 64 t-cols] per warp, split-tf32 (3 MMAs/step)
        float s[8][4] = {};
        #pragma unroll
        for (int k8 = 0; k8 < 8; k8++) {
            int k0 = k8 * 8;
            #pragma unroll
            for (int nt = 0; nt < 8; nt++) {
                float q0 = Qb[(nt * 8 + r) * LDQ + k0 + cc];
                float q1 = Qb[(nt * 8 + r) * LDQ + k0 + cc + 4];
                float q0h = rtf32(q0), q1h = rtf32(q1);
                uint32_t b0h = __float_as_uint(q0h);
                uint32_t b1h = __float_as_uint(q1h);
                uint32_t b0l = __float_as_uint(rtf32(q0 - q0h));
                uint32_t b1l = __float_as_uint(rtf32(q1 - q1h));
                mma_tf32(s[nt], kfh[k8], b0h, b1h);
                mma_tf32(s[nt], kfh[k8], b0l, b1l);
                mma_tf32(s[nt], kfl[k8], b0h, b1h);
            }
        }

        // online softmax over t (rows fully in-warp: quad shfl reduce)
        float mx0 = -1e30f, mx1 = -1e30f;
        #pragma unroll
        for (int nt = 0; nt < 8; nt++) {
            mx0 = fmaxf(mx0, fmaxf(s[nt][0], s[nt][1]));
            mx1 = fmaxf(mx1, fmaxf(s[nt][2], s[nt][3]));
        }
        mx0 = fmaxf(mx0, __shfl_xor_sync(0xffffffffu, mx0, 1));
        mx0 = fmaxf(mx0, __shfl_xor_sync(0xffffffffu, mx0, 2));
        mx1 = fmaxf(mx1, __shfl_xor_sync(0xffffffffu, mx1, 1));
        mx1 = fmaxf(mx1, __shfl_xor_sync(0xffffffffu, mx1, 2));
        float mn0 = fmaxf(mrow0, mx0), mn1 = fmaxf(mrow1, mx1);
        float a0 = __expf(mrow0 - mn0), a1 = __expf(mrow1 - mn1);
        mrow0 = mn0; mrow1 = mn1;

        float ps0 = 0.f, ps1 = 0.f;
        #pragma unroll
        for (int nt = 0; nt < 8; nt++) {
            float p0 = __expf(s[nt][0] - mn0);
            float p1 = __expf(s[nt][1] - mn0);
            float p2 = __expf(s[nt][2] - mn1);
            float p3 = __expf(s[nt][3] - mn1);
            ps0 += p0 + p1;
            ps1 += p2 + p3;
            float2 w0 = { rtf32(p0), rtf32(p1) };
            float2 w1 = { rtf32(p2), rtf32(p3) };
            *(float2*)&KP[(rb    ) * LDP + nt * 8 + 2 * cc] = w0;
            *(float2*)&KP[(rb + 8) * LDP + nt * 8 + 2 * cc] = w1;
        }
        ps0 += __shfl_xor_sync(0xffffffffu, ps0, 1);
        ps0 += __shfl_xor_sync(0xffffffffu, ps0, 2);
        ps1 += __shfl_xor_sync(0xffffffffu, ps1, 1);
        ps1 += __shfl_xor_sync(0xffffffffu, ps1, 2);
        lrow0 = lrow0 * a0 + ps0;
        lrow1 = lrow1 * a1 + ps1;
        #pragma unroll
        for (int nt = 0; nt < 8; nt++) {
            o[nt][0] *= a0; o[nt][1] *= a0;
            o[nt][2] *= a1; o[nt][3] *= a1;
        }
        __syncwarp();   // this warp's P rows visible (warp-private region)

        // O += P x V : A-frags of P from smem (tf32 already), V rna-rounded
        #pragma unroll
        for (int k8 = 0; k8 < 8; k8++) {
            int k0 = k8 * 8;
            uint32_t pa[4];
            pa[0] = __float_as_uint(KP[(rb    ) * LDP + k0 + cc]);
            pa[1] = __float_as_uint(KP[(rb + 8) * LDP + k0 + cc]);
            pa[2] = __float_as_uint(KP[(rb    ) * LDP + k0 + cc + 4]);
            pa[3] = __float_as_uint(KP[(rb + 8) * LDP + k0 + cc + 4]);
            #pragma unroll
            for (int nt = 0; nt < 8; nt++) {
                uint32_t b0 = __float_as_uint(rtf32(Vb[(k0 + cc    ) * LDV + nt * 8 + r]));
                uint32_t b1 = __float_as_uint(rtf32(Vb[(k0 + cc + 4) * LDV + nt * 8 + r]));
                mma_tf32(o[nt], pa, b0, b1);
            }
        }
        CP_WAIT0();
        __syncthreads();    // next Q/V buffers resident; P region safe (warp-private)
    }

    float i0 = 1.f / lrow0, i1 = 1.f / lrow1;
    float* orow0 = o_out + (size_t)(b * Ss + s0 + rb) * E + hh * 64;
    float* orow1 = orow0 + 8 * (size_t)E;
    #pragma unroll
    for (int nt = 0; nt < 8; nt++) {
        int col = nt * 8 + 2 * cc;
        float2 v0 = { rtf32(o[nt][0] * i0), rtf32(o[nt][1] * i0) };
        float2 v1 = { rtf32(o[nt][2] * i1), rtf32(o[nt][3] * i1) };
        *(float2*)&orow0[col] = v0;
        *(float2*)&orow1[col] = v1;
    }
}

// ---------------- host launch ----------------
extern "C" void kernel_launch(void* const* d_in, const int* in_sizes, int n_in,
                              void* d_out, int out_size) {
    const float* x     = (const float*)d_in[0];
    const float* Wq    = (const float*)d_in[1];
    const float* bq    = (const float*)d_in[2];
    const float* Wk    = (const float*)d_in[3];
    const float* bk    = (const float*)d_in[4];
    const float* Wv    = (const float*)d_in[5];
    const float* bv    = (const float*)d_in[6];
    const float* Wo    = (const float*)d_in[7];
    const float* bo    = (const float*)d_in[8];
    const float* ln1_g = (const float*)d_in[9];
    const float* ln1_b = (const float*)d_in[10];
    const float* ln2_g = (const float*)d_in[11];
    const float* ln2_b = (const float*)d_in[12];
    const float* W1    = (const float*)d_in[13];
    const float* b1    = (const float*)d_in[14];
    const float* W2    = (const float*)d_in[15];
    const float* b2    = (const float*)d_in[16];
    float* out = (float*)d_out;

    float *p_h, *p_qkv, *p_Wqkv, *p_bqkv, *p_WoT, *p_W1T, *p_W2T, *p_o, *p_x1, *p_h2, *p_m1;
    cudaGetSymbolAddress((void**)&p_h,    g_h);
    cudaGetSymbolAddress((void**)&p_qkv,  g_qkv);
    cudaGetSymbolAddress((void**)&p_Wqkv, g_Wqkv);
    cudaGetSymbolAddress((void**)&p_bqkv, g_bqkv);
    cudaGetSymbolAddress((void**)&p_WoT,  g_WoT);
    cudaGetSymbolAddress((void**)&p_W1T,  g_W1T);
    cudaGetSymbolAddress((void**)&p_W2T,  g_W2T);
    cudaGetSymbolAddress((void**)&p_o,    g_o);
    cudaGetSymbolAddress((void**)&p_x1,   g_x1);
    cudaGetSymbolAddress((void**)&p_h2,   g_h2);
    cudaGetSymbolAddress((void**)&p_m1,   g_m1);

    cudaFuncSetAttribute(gemm_tc<false, false>, cudaFuncAttributeMaxDynamicSharedMemorySize, GEMM_SMEM);
    cudaFuncSetAttribute(gemm_tc<true,  true>,  cudaFuncAttributeMaxDynamicSharedMemorySize, GEMM_SMEM);
    cudaFuncSetAttribute(attn_mma_kernel,       cudaFuncAttributeMaxDynamicSharedMemorySize, ATT_SMEM);

    // 1. pack fused QKV weight (transposed, tf32) + bias; transpose Wo, W1, W2 (tf32)
    pack_qkv_kernel<<<(3 * E * E + 255) / 256, 256>>>(Wq, Wk, Wv, bq, bk, bv);
    transpose_kernel<<<dim3(E / 32, E / 32),  dim3(32, 8)>>>(Wo, p_WoT, E, E);
    transpose_kernel<<<dim3(E / 32, Ff / 32), dim3(32, 8)>>>(W1, p_W1T, E, Ff);
    transpose_kernel<<<dim3(Ff / 32, E / 32), dim3(32, 8)>>>(W2, p_W2T, Ff, E);

    // 2. LN1
    ln_kernel<<<NT, 256>>>(x, ln1_g, ln1_b, p_h);

    // 3. fused QKV projection: [4096,1024] @ [1024,3072]  (fp32 out -> split-tf32 attn)
    gemm_tc<false, false><<<dim3(3 * E / 128, NT / 128), 256, GEMM_SMEM>>>(p_h, p_Wqkv, p_bqkv, nullptr, p_qkv, NT, 3 * E, E);

    // 4. attention (split-tf32 S, tf32 PV)
    attn_mma_kernel<<<dim3(Ss / 128, H * Bb), 256, ATT_SMEM>>>(p_qkv, p_o);

    // 5. output projection + residual
    gemm_tc<false, false><<<dim3(E / 128, NT / 128), 256, GEMM_SMEM>>>(p_o, p_WoT, bo, x, p_x1, NT, E, E);

    // 6. LN2
    ln_kernel<<<NT, 256>>>(p_x1, ln2_g, ln2_b, p_h2);

    // 7. MLP up + ReLU (output tf32-rounded: feeds GEMM 8 as A)
    gemm_tc<true, true><<<dim3(Ff / 128, NT / 128), 256, GEMM_SMEM>>>(p_h2, p_W1T, b1, nullptr, p_m1, NT, Ff, E);

    // 8. MLP down + residual -> output
    gemm_tc<false, false><<<dim3(E / 128, NT / 128), 256, GEMM_SMEM>>>(p_m1, p_W2T, b2, p_x1, out, NT, E, Ff);
}